// round 17
// baseline (speedup 1.0000x reference)
#include <cuda_runtime.h>
#include <cuda_bf16.h>
#include <cstdint>

#define NA 8192
#define NN 65536
#define NE 262144
#define DD 128
#define GN_EPS 1e-5f
#define TILE 128
#define STR 132
#define NTH 256
#define WCH 16
#define SWBUF (WCH * 128)

// ---------------- scratch (device globals) ----------------
__device__ __align__(16) float g_qc[NA * DD];
__device__ __align__(16) float g_nc[NN * DD];
__device__ __align__(16) float g_a[NA * DD];
__device__ __align__(16) float g_actors[NA * DD];
// pre-split bf16 weights, row-major [oc][k]: [mat][hi/lo][16384]
// mats: 0=dist1, 1=ctx0_d, 2=ctx1, 3=ctx0_c (node)
__device__ __align__(16) __nv_bfloat16 g_w[4][2][16384];

// ---------------- small helpers ----------------
__device__ __forceinline__ uint32_t smem_to_u32(const void* p) {
    uint32_t a;
    asm("{ .reg .u64 t; cvta.to.shared.u64 t, %1; cvt.u32.u64 %0, t; }" : "=r"(a) : "l"(p));
    return a;
}
__device__ __forceinline__ void redv2(const float* p, float a, float b) {
    asm volatile("red.global.add.v2.f32 [%0], {%1, %2};"
                 :: "l"(p), "f"(a), "f"(b) : "memory");
}
__device__ __forceinline__ void bf16_split(float v, __nv_bfloat16& h, __nv_bfloat16& l) {
    h = __float2bfloat16_rn(v);
    l = __float2bfloat16_rn(v - __bfloat162float(h));
}
__device__ __forceinline__ uint32_t pkbf(__nv_bfloat16 a, __nv_bfloat16 b) {
    return (uint32_t)__bfloat16_as_ushort(a) | ((uint32_t)__bfloat16_as_ushort(b) << 16);
}
__device__ __forceinline__ void ldsm_x4(uint32_t& r0, uint32_t& r1, uint32_t& r2, uint32_t& r3,
                                        uint32_t addr) {
    asm volatile("ldmatrix.sync.aligned.m8n8.x4.shared.b16 {%0,%1,%2,%3}, [%4];"
                 : "=r"(r0), "=r"(r1), "=r"(r2), "=r"(r3) : "r"(addr));
}
__device__ __forceinline__ void ldsm_x2(uint32_t& r0, uint32_t& r1, uint32_t addr) {
    asm volatile("ldmatrix.sync.aligned.m8n8.x2.shared.b16 {%0,%1}, [%2];"
                 : "=r"(r0), "=r"(r1) : "r"(addr));
}
__device__ __forceinline__ void mma16816(float* c, uint32_t a0, uint32_t a1, uint32_t a2,
                                         uint32_t a3, uint32_t b0, uint32_t b1) {
    asm volatile("mma.sync.aligned.m16n8k16.row.col.f32.bf16.bf16.f32 "
                 "{%0,%1,%2,%3}, {%4,%5,%6,%7}, {%8,%9}, {%0,%1,%2,%3};"
                 : "+f"(c[0]), "+f"(c[1]), "+f"(c[2]), "+f"(c[3])
                 : "r"(a0), "r"(a1), "r"(a2), "r"(a3), "r"(b0), "r"(b1));
}
__device__ __forceinline__ void cpa16(uint32_t s, const void* g) {
    asm volatile("cp.async.cg.shared.global [%0], [%1], 16;" :: "r"(s), "l"(g));
}
#define CPA_COMMIT() asm volatile("cp.async.commit_group;" ::: "memory")
#define CPA_WAIT(n) asm volatile("cp.async.wait_group %0;" :: "n"(n) : "memory")

// ================= scalar fp32 machinery (R8, known good; pre/post) =================
__device__ __forceinline__ void ffma2(unsigned long long& acc, unsigned long long w,
                                      unsigned long long a) {
    asm volatile("fma.rn.f32x2 %0, %1, %2, %0;" : "+l"(acc) : "l"(w), "l"(a));
}
__device__ __forceinline__ unsigned long long pack2(float x) {
    unsigned long long r;
    asm("mov.b64 %0, {%1, %1};" : "=l"(r) : "f"(x));
    return r;
}
__device__ __forceinline__ float2 unpack2(unsigned long long v) {
    float2 r;
    asm("mov.b64 {%0, %1}, %2;" : "=f"(r.x), "=f"(r.y) : "l"(v));
    return r;
}
struct TG {
    int t, lane, og, ocblk, eRow0, o0;
};
__device__ __forceinline__ TG tgeom() {
    TG g;
    g.t = threadIdx.x;
    const int warp = g.t >> 5;
    g.lane = g.t & 31;
    g.og = g.lane & 7;
    g.ocblk = warp & 1;
    g.eRow0 = (warp >> 1) * 32 + (g.lane >> 3) * 8;
    g.o0 = g.ocblk * 64 + g.og * 8;
    return g;
}
__device__ __forceinline__ void gemm8x8(const float* __restrict__ W, int ldW,
                                        const float* sAct, float* sW,
                                        unsigned long long (&acc)[8][4], const TG& g) {
    const int oc = g.t & 127;
    const int kh = (g.t >> 7) * 8;
    const int nch = DD >> 4;
    float4 w0 = *(const float4*)(W + oc * ldW + kh);
    float4 w1 = *(const float4*)(W + oc * ldW + kh + 4);
    for (int c = 0; c < nch; c++) {
        float* sb = sW + (c & 1) * SWBUF;
        sb[(kh + 0) * 128 + oc] = w0.x;
        sb[(kh + 1) * 128 + oc] = w0.y;
        sb[(kh + 2) * 128 + oc] = w0.z;
        sb[(kh + 3) * 128 + oc] = w0.w;
        sb[(kh + 4) * 128 + oc] = w1.x;
        sb[(kh + 5) * 128 + oc] = w1.y;
        sb[(kh + 6) * 128 + oc] = w1.z;
        sb[(kh + 7) * 128 + oc] = w1.w;
        __syncthreads();
        if (c + 1 < nch) {
            const float* Wp = W + oc * ldW + ((c + 1) << 4) + kh;
            w0 = *(const float4*)(Wp);
            w1 = *(const float4*)(Wp + 4);
        }
        const int k0 = c << 4;
#pragma unroll
        for (int kq = 0; kq < 4; kq++) {
            float4 a4[8];
#pragma unroll
            for (int i = 0; i < 8; i++)
                a4[i] = *(const float4*)(sAct + (g.eRow0 + i) * STR + k0 + kq * 4);
#pragma unroll
            for (int kk = 0; kk < 4; kk++) {
                const int k = kq * 4 + kk;
                const ulonglong2 wa = *(const ulonglong2*)(sb + k * 128 + g.o0);
                const ulonglong2 wb = *(const ulonglong2*)(sb + k * 128 + g.o0 + 4);
#pragma unroll
                for (int i = 0; i < 8; i++) {
                    const float av = (kk == 0) ? a4[i].x : (kk == 1) ? a4[i].y
                                   : (kk == 2) ? a4[i].z : a4[i].w;
                    const unsigned long long aa = pack2(av);
                    ffma2(acc[i][0], wa.x, aa);
                    ffma2(acc[i][1], wa.y, aa);
                    ffma2(acc[i][2], wb.x, aa);
                    ffma2(acc[i][3], wb.y, aa);
                }
            }
        }
    }
}
template <int MODE>
__device__ __forceinline__ void gn_regs(const unsigned long long (&acc)[8][4],
                                        float* dst, int dstStride,
                                        const float* __restrict__ gamma,
                                        const float* __restrict__ beta,
                                        float* sRed, const TG& g, const float* res) {
    const float4 g0 = *(const float4*)(gamma + g.o0);
    const float4 g1 = *(const float4*)(gamma + g.o0 + 4);
    const float4 b0 = *(const float4*)(beta + g.o0);
    const float4 b1 = *(const float4*)(beta + g.o0 + 4);
#pragma unroll
    for (int i = 0; i < 8; i++) {
        float s = 0.f, s2 = 0.f;
#pragma unroll
        for (int j = 0; j < 4; j++) {
            float2 p = unpack2(acc[i][j]);
            s += p.x + p.y;
            s2 += p.x * p.x + p.y * p.y;
        }
#pragma unroll
        for (int o = 4; o > 0; o >>= 1) {
            s += __shfl_xor_sync(0xffffffffu, s, o);
            s2 += __shfl_xor_sync(0xffffffffu, s2, o);
        }
        if (g.og == 0) {
            sRed[(g.eRow0 + i) * 4 + g.ocblk * 2 + 0] = s;
            sRed[(g.eRow0 + i) * 4 + g.ocblk * 2 + 1] = s2;
        }
    }
    __syncthreads();
#pragma unroll
    for (int i = 0; i < 8; i++) {
        const int e = g.eRow0 + i;
        const float s = sRed[e * 4 + 0] + sRed[e * 4 + 2];
        const float s2 = sRed[e * 4 + 1] + sRed[e * 4 + 3];
        const float mu = s * (1.f / 128.f);
        const float var = s2 * (1.f / 128.f) - mu * mu;
        const float rstd = rsqrtf(var + GN_EPS);
        float v[8];
#pragma unroll
        for (int j = 0; j < 4; j++) {
            float2 p = unpack2(acc[i][j]);
            v[2 * j] = p.x;
            v[2 * j + 1] = p.y;
        }
        float y[8];
        y[0] = (v[0] - mu) * rstd * g0.x + b0.x;
        y[1] = (v[1] - mu) * rstd * g0.y + b0.y;
        y[2] = (v[2] - mu) * rstd * g0.z + b0.z;
        y[3] = (v[3] - mu) * rstd * g0.w + b0.w;
        y[4] = (v[4] - mu) * rstd * g1.x + b1.x;
        y[5] = (v[5] - mu) * rstd * g1.y + b1.y;
        y[6] = (v[6] - mu) * rstd * g1.z + b1.z;
        y[7] = (v[7] - mu) * rstd * g1.w + b1.w;
        if (MODE == 2) {
            const float4 r0 = *(const float4*)(res + (size_t)e * DD + g.o0);
            const float4 r1 = *(const float4*)(res + (size_t)e * DD + g.o0 + 4);
            y[0] += r0.x; y[1] += r0.y; y[2] += r0.z; y[3] += r0.w;
            y[4] += r1.x; y[5] += r1.y; y[6] += r1.z; y[7] += r1.w;
        }
#pragma unroll
        for (int j = 0; j < 8; j++) y[j] = fmaxf(y[j], 0.f);
        *(float4*)(dst + (size_t)e * dstStride + g.o0) = make_float4(y[0], y[1], y[2], y[3]);
        *(float4*)(dst + (size_t)e * dstStride + g.o0 + 4) = make_float4(y[4], y[5], y[6], y[7]);
    }
}
__device__ __forceinline__ void store_acc_raw(const unsigned long long (&acc)[8][4],
                                              float* dst, int stride, const TG& g) {
#pragma unroll
    for (int i = 0; i < 8; i++) {
        float v[8];
#pragma unroll
        for (int j = 0; j < 4; j++) {
            float2 p = unpack2(acc[i][j]);
            v[2 * j] = p.x;
            v[2 * j + 1] = p.y;
        }
        float* d = dst + (size_t)(g.eRow0 + i) * stride + g.o0;
        *(float4*)(d) = make_float4(v[0], v[1], v[2], v[3]);
        *(float4*)(d + 4) = make_float4(v[4], v[5], v[6], v[7]);
    }
}
#define ZACC8(acc)                                         \
    _Pragma("unroll") for (int _i = 0; _i < 8; _i++)       \
        _Pragma("unroll") for (int _j = 0; _j < 4; _j++)   \
            acc[_i][_j] = 0ull;

// ---------------- pre / post (scalar fp32, proven) ----------------
__global__ void __launch_bounds__(NTH, 1)
pre_kernel(const float* __restrict__ actors_in, const float* __restrict__ qW,
           const float* __restrict__ qg, const float* __restrict__ qb,
           const float* __restrict__ c0Wq, const float* __restrict__ aW, int blk) {
    extern __shared__ float sm[];
    float* sA = sm;
    float* sQ = sA + TILE * STR;
    float* sW = sQ + TILE * STR;
    float* sRed = sW + 2 * SWBUF;
    const float* cur = blk ? g_actors : actors_in;
    const TG g = tgeom();
    const int r0 = blockIdx.x * TILE;
    for (int idx = g.t; idx < TILE * 32; idx += NTH) {
        int e = idx >> 5, c4 = idx & 31;
        *(float4*)(sA + e * STR + c4 * 4) =
            *(const float4*)(cur + (size_t)(r0 + e) * DD + c4 * 4);
    }
    __syncthreads();
    unsigned long long acc[8][4];
    ZACC8(acc);
    gemm8x8(qW, DD, sA, sW, acc, g);
    gn_regs<1>(acc, sQ, STR, qg, qb, sRed, g, nullptr);
    ZACC8(acc);
    gemm8x8(c0Wq, 3 * DD, sQ, sW, acc, g);
    store_acc_raw(acc, g_qc + (size_t)r0 * DD, DD, g);
    ZACC8(acc);
    gemm8x8(aW, DD, sA, sW, acc, g);
    store_acc_raw(acc, g_a + (size_t)r0 * DD, DD, g);
}

__global__ void __launch_bounds__(NTH, 1)
post_kernel(const float* __restrict__ actors_in, const float* __restrict__ ng,
            const float* __restrict__ nb, const float* __restrict__ lW,
            const float* __restrict__ lg, const float* __restrict__ lb,
            float* __restrict__ out, int blk) {
    extern __shared__ float sm[];
    float* sA = sm;
    float* sW = sA + TILE * STR;
    float* sRed = sW + 2 * SWBUF;
    const float* cur = blk ? g_actors : actors_in;
    float* nxt = blk ? out : g_actors;
    const TG g = tgeom();
    const int t = g.t;
    const int r0 = blockIdx.x * TILE;
    {
        const int warp = t >> 5, lane = t & 31;
        for (int e = warp; e < TILE; e += 8) {
            const float* row = g_a + (size_t)(r0 + e) * DD;
            float v[4], s = 0.f, s2 = 0.f;
#pragma unroll
            for (int j = 0; j < 4; j++) {
                v[j] = row[lane + 32 * j];
                s += v[j];
                s2 += v[j] * v[j];
            }
#pragma unroll
            for (int o = 16; o > 0; o >>= 1) {
                s += __shfl_xor_sync(0xffffffffu, s, o);
                s2 += __shfl_xor_sync(0xffffffffu, s2, o);
            }
            const float mu = s * (1.f / 128.f);
            const float var = s2 * (1.f / 128.f) - mu * mu;
            const float rstd = rsqrtf(var + GN_EPS);
#pragma unroll
            for (int j = 0; j < 4; j++) {
                const int ch = lane + 32 * j;
                sA[e * STR + ch] = fmaxf((v[j] - mu) * rstd * ng[ch] + nb[ch], 0.f);
            }
        }
    }
    __syncthreads();
    unsigned long long acc[8][4];
    ZACC8(acc);
    gemm8x8(lW, DD, sA, sW, acc, g);
    gn_regs<2>(acc, nxt + (size_t)r0 * DD, DD, lg, lb, sRed, g, cur + (size_t)r0 * DD);
}

// ---------------- weight prep: split fp32 -> bf16 hi/lo (row-major [oc][k]) ----------------
__global__ void __launch_bounds__(256, 4)
wprep_kernel(const float* __restrict__ d1W, const float* __restrict__ c0Wd,
             const float* __restrict__ c1W) {
    const int idx = blockIdx.x * 256 + threadIdx.x;  // 4*16384
    const int m = idx / 16384, e = idx % 16384;
    const int row = e >> 7, col = e & 127;
    float v;
    if (m == 0) v = d1W[row * 128 + col];
    else if (m == 1) v = c0Wd[row * 384 + col];
    else if (m == 2) v = c1W[row * 128 + col];
    else v = c0Wd[row * 384 + 256 + col];  // ctx0_c (node weights)
    __nv_bfloat16 h, l;
    bf16_split(v, h, l);
    g_w[m][0][e] = h;
    g_w[m][1][e] = l;
}

// ---------------- mma.sync tiles ----------------
#define RSB 272
#define ABYTES (128 * RSB)  // 34816

__device__ __forceinline__ void copy_w_async(uint32_t dH, uint32_t dL, int mat, int t) {
    for (int i = t; i < 2048; i += NTH) {
        const int row = i >> 4, c = i & 15;
        cpa16(dH + row * RSB + c * 16, &g_w[mat][0][row * 128 + c * 8]);
        cpa16(dL + row * RSB + c * 16, &g_w[mat][1][row * 128 + c * 8]);
    }
}

// 4m x 2n warp grid: warp owns rows [wm*32, wm*32+32), cols [wn*64, wn*64+64)
__device__ __forceinline__ void wgemm2(float (&acc)[2][8][4], uint32_t aH, uint32_t aL,
                                       uint32_t wH, uint32_t wL, int wm, int wn, int lane) {
    const uint32_t ao = (uint32_t)((lane & 15) * RSB + ((lane >> 4) & 1) * 16 + wm * 32 * RSB);
    const uint32_t bo = (uint32_t)((lane & 7) * RSB + ((lane >> 3) & 1) * 16 + wn * 64 * RSB);
#pragma unroll
    for (int k = 0; k < 8; k++) {
        const uint32_t kb = (uint32_t)k * 32;
        uint32_t ah[2][4], al[2][4];
        ldsm_x4(ah[0][0], ah[0][1], ah[0][2], ah[0][3], aH + ao + kb);
        ldsm_x4(ah[1][0], ah[1][1], ah[1][2], ah[1][3], aH + ao + 16 * RSB + kb);
        ldsm_x4(al[0][0], al[0][1], al[0][2], al[0][3], aL + ao + kb);
        ldsm_x4(al[1][0], al[1][1], al[1][2], al[1][3], aL + ao + 16 * RSB + kb);
#pragma unroll
        for (int ni = 0; ni < 8; ni++) {
            uint32_t bh0, bh1, bl0, bl1;
            ldsm_x2(bh0, bh1, wH + bo + (uint32_t)(ni * 8 * RSB) + kb);
            ldsm_x2(bl0, bl1, wL + bo + (uint32_t)(ni * 8 * RSB) + kb);
#pragma unroll
            for (int mi = 0; mi < 2; mi++) {
                mma16816(acc[mi][ni], ah[mi][0], ah[mi][1], ah[mi][2], ah[mi][3], bh0, bh1);
                mma16816(acc[mi][ni], ah[mi][0], ah[mi][1], ah[mi][2], ah[mi][3], bl0, bl1);
                mma16816(acc[mi][ni], al[mi][0], al[mi][1], al[mi][2], al[mi][3], bh0, bh1);
            }
        }
    }
}

#define ZACC2(acc)                                           \
    _Pragma("unroll") for (int _m = 0; _m < 2; _m++)         \
        _Pragma("unroll") for (int _i = 0; _i < 8; _i++)     \
            _Pragma("unroll") for (int _j = 0; _j < 4; _j++) \
                acc[_m][_i][_j] = 0.f;

// GroupNorm from mma accumulators; cross-warp (2 col-halves) via sRed; write split bf16.
// ADDM: add qc[hi[row]] + nc[wi[row]] read from global (L2-resident).
template <bool ADDM>
__device__ __forceinline__ void gn_mma2(float (&acc)[2][8][4], const int* shi, const int* swi,
                                        const float* __restrict__ gamma,
                                        const float* __restrict__ beta,
                                        float* sRed, char* sAh, char* sAl,
                                        int wm, int wn, int lane) {
    const int rbase = wm * 32, cbase = wn * 64;
    const int cb = 2 * (lane & 3);
    if (ADDM) {
#pragma unroll
        for (int mi = 0; mi < 2; mi++) {
            const int rl = rbase + mi * 16 + (lane >> 2), rh = rl + 8;
            const float* ql = g_qc + (size_t)shi[rl] * DD;
            const float* nl = g_nc + (size_t)swi[rl] * DD;
            const float* qh = g_qc + (size_t)shi[rh] * DD;
            const float* nh = g_nc + (size_t)swi[rh] * DD;
#pragma unroll
            for (int ni = 0; ni < 8; ni++) {
                const int col = cbase + ni * 8 + cb;
                const float2 a = *(const float2*)(ql + col);
                const float2 b = *(const float2*)(nl + col);
                acc[mi][ni][0] += a.x + b.x;
                acc[mi][ni][1] += a.y + b.y;
                const float2 c = *(const float2*)(qh + col);
                const float2 d = *(const float2*)(nh + col);
                acc[mi][ni][2] += c.x + d.x;
                acc[mi][ni][3] += c.y + d.y;
            }
        }
    }
#pragma unroll
    for (int mi = 0; mi < 2; mi++) {
        float sl = 0.f, s2l = 0.f, sh = 0.f, s2h = 0.f;
#pragma unroll
        for (int ni = 0; ni < 8; ni++) {
            sl += acc[mi][ni][0] + acc[mi][ni][1];
            s2l += acc[mi][ni][0] * acc[mi][ni][0] + acc[mi][ni][1] * acc[mi][ni][1];
            sh += acc[mi][ni][2] + acc[mi][ni][3];
            s2h += acc[mi][ni][2] * acc[mi][ni][2] + acc[mi][ni][3] * acc[mi][ni][3];
        }
#pragma unroll
        for (int o = 1; o <= 2; o <<= 1) {
            sl += __shfl_xor_sync(0xffffffffu, sl, o);
            s2l += __shfl_xor_sync(0xffffffffu, s2l, o);
            sh += __shfl_xor_sync(0xffffffffu, sh, o);
            s2h += __shfl_xor_sync(0xffffffffu, s2h, o);
        }
        const int rl = rbase + mi * 16 + (lane >> 2), rh = rl + 8;
        if ((lane & 3) == 0) {
            sRed[rl * 4 + wn * 2 + 0] = sl;
            sRed[rl * 4 + wn * 2 + 1] = s2l;
            sRed[rh * 4 + wn * 2 + 0] = sh;
            sRed[rh * 4 + wn * 2 + 1] = s2h;
        }
    }
    __syncthreads();
#pragma unroll
    for (int mi = 0; mi < 2; mi++) {
        const int rl = rbase + mi * 16 + (lane >> 2), rh = rl + 8;
        const float sl = sRed[rl * 4 + 0] + sRed[rl * 4 + 2];
        const float s2l = sRed[rl * 4 + 1] + sRed[rl * 4 + 3];
        const float sh = sRed[rh * 4 + 0] + sRed[rh * 4 + 2];
        const float s2h = sRed[rh * 4 + 1] + sRed[rh * 4 + 3];
        const float mul = sl * (1.f / 128.f);
        const float rsl = rsqrtf(s2l * (1.f / 128.f) - mul * mul + GN_EPS);
        const float muh = sh * (1.f / 128.f);
        const float rsh = rsqrtf(s2h * (1.f / 128.f) - muh * muh + GN_EPS);
#pragma unroll
        for (int ni = 0; ni < 8; ni++) {
            const int col = cbase + ni * 8 + cb;
            const float2 g2 = *(const float2*)(gamma + col);
            const float2 b2 = *(const float2*)(beta + col);
            const float y0 = fmaxf((acc[mi][ni][0] - mul) * rsl * g2.x + b2.x, 0.f);
            const float y1 = fmaxf((acc[mi][ni][1] - mul) * rsl * g2.y + b2.y, 0.f);
            const float y2 = fmaxf((acc[mi][ni][2] - muh) * rsh * g2.x + b2.x, 0.f);
            const float y3 = fmaxf((acc[mi][ni][3] - muh) * rsh * g2.y + b2.y, 0.f);
            __nv_bfloat16 h0, l0, h1, l1, h2, l2, h3, l3;
            bf16_split(y0, h0, l0);
            bf16_split(y1, h1, l1);
            bf16_split(y2, h2, l2);
            bf16_split(y3, h3, l3);
            *(uint32_t*)(sAh + rl * RSB + col * 2) = pkbf(h0, h1);
            *(uint32_t*)(sAl + rl * RSB + col * 2) = pkbf(l0, l1);
            *(uint32_t*)(sAh + rh * RSB + col * 2) = pkbf(h2, h3);
            *(uint32_t*)(sAl + rh * RSB + col * 2) = pkbf(l2, l3);
        }
    }
}

// ---------------- node precompute (mma): g_nc = nodes @ ctx0_Wc^T ----------------
#define NOD_AH 0
#define NOD_AL ABYTES
#define NOD_WH (2 * ABYTES)
#define NOD_WL (3 * ABYTES)
#define SMEM_NODE (4 * ABYTES)

__global__ void __launch_bounds__(NTH, 1)
node_kernel(const float* __restrict__ nodes) {
    extern __shared__ char smc[];
    const uint32_t sb = smem_to_u32(smc);
    const int t = threadIdx.x, lane = t & 31, wid = t >> 5;
    const int wm = wid >> 1, wn = wid & 1;
    const int r0 = blockIdx.x * TILE;

    copy_w_async(sb + NOD_WH, sb + NOD_WL, 3, t);
    CPA_COMMIT();
    // convert nodes rows -> split bf16 A tiles
    {
        const int r = t >> 1, c0 = (t & 1) * 64;
        const float* src = nodes + (size_t)(r0 + r) * DD + c0;
#pragma unroll
        for (int gb = 0; gb < 8; gb++) {
            const float4 v4 = *(const float4*)(src + gb * 8);
            const float4 v4b = *(const float4*)(src + gb * 8 + 4);
            __nv_bfloat16 h8[8], l8[8];
            bf16_split(v4.x, h8[0], l8[0]);
            bf16_split(v4.y, h8[1], l8[1]);
            bf16_split(v4.z, h8[2], l8[2]);
            bf16_split(v4.w, h8[3], l8[3]);
            bf16_split(v4b.x, h8[4], l8[4]);
            bf16_split(v4b.y, h8[5], l8[5]);
            bf16_split(v4b.z, h8[6], l8[6]);
            bf16_split(v4b.w, h8[7], l8[7]);
            const int off = r * RSB + (c0 + gb * 8) * 2;
            *(uint4*)(smc + NOD_AH + off) = *(uint4*)h8;
            *(uint4*)(smc + NOD_AL + off) = *(uint4*)l8;
        }
    }
    CPA_WAIT(0);
    __syncthreads();
    float acc[2][8][4];
    ZACC2(acc);
    wgemm2(acc, sb + NOD_AH, sb + NOD_AL, sb + NOD_WH, sb + NOD_WL, wm, wn, lane);
    const int cb = 2 * (lane & 3);
#pragma unroll
    for (int mi = 0; mi < 2; mi++) {
        const int rl = wm * 32 + mi * 16 + (lane >> 2), rh = rl + 8;
        float* dl = g_nc + (size_t)(r0 + rl) * DD;
        float* dh = g_nc + (size_t)(r0 + rh) * DD;
#pragma unroll
        for (int ni = 0; ni < 8; ni++) {
            const int col = wn * 64 + ni * 8 + cb;
            *(float2*)(dl + col) = make_float2(acc[mi][ni][0], acc[mi][ni][1]);
            *(float2*)(dh + col) = make_float2(acc[mi][ni][2], acc[mi][ni][3]);
        }
    }
}

// ---------------- edge kernel (mma, double-buffered weights) ----------------
#define OFF_AH 0
#define OFF_AL ABYTES
#define OFF_W0H (2 * ABYTES)
#define OFF_W0L (3 * ABYTES)
#define OFF_W1H (4 * ABYTES)
#define OFF_W1L (5 * ABYTES)
#define OFF_SRED (6 * ABYTES)                 // 128*4 floats = 2048 B
#define OFF_HI (OFF_SRED + 2048)
#define OFF_WI (OFF_HI + 512)
#define OFF_DX (OFF_WI + 512)
#define OFF_DY (OFF_DX + 512)
#define SMEM_EDGE (OFF_DY + 512)

__global__ void __launch_bounds__(NTH, 1)
edge_kernel(const float* __restrict__ actor_ctrs, const float* __restrict__ node_ctrs,
            const int* __restrict__ hi, const int* __restrict__ wi,
            const float* __restrict__ d0W, const float* __restrict__ d0b,
            const float* __restrict__ d1g, const float* __restrict__ d1b,
            const float* __restrict__ c0g, const float* __restrict__ c0b) {
    extern __shared__ char smc[];
    const uint32_t sb = smem_to_u32(smc);
    char* sAh = smc + OFF_AH;
    char* sAl = smc + OFF_AL;
    float* sRed = (float*)(smc + OFF_SRED);
    int* shi = (int*)(smc + OFF_HI);
    int* swi = (int*)(smc + OFF_WI);
    float* sdx = (float*)(smc + OFF_DX);
    float* sdy = (float*)(smc + OFF_DY);

    const int t = threadIdx.x, lane = t & 31, wid = t >> 5;
    const int wm = wid >> 1, wn = wid & 1;
    const int e0 = blockIdx.x * TILE;

    // prefetch GEMM1+GEMM2 weights while we set up
    copy_w_async(sb + OFF_W0H, sb + OFF_W0L, 0, t);
    CPA_COMMIT();
    copy_w_async(sb + OFF_W1H, sb + OFF_W1L, 1, t);
    CPA_COMMIT();

    if (t < TILE) {
        const int h = hi[e0 + t], w = wi[e0 + t];
        shi[t] = h;
        swi[t] = w;
        sdx[t] = actor_ctrs[2 * h] - node_ctrs[2 * w];
        sdy[t] = actor_ctrs[2 * h + 1] - node_ctrs[2 * w + 1];
    }
    __syncthreads();
    // H1 = relu(dist0) -> split bf16 A tiles
    {
        const int r = t >> 1, c0 = (t & 1) * 64;
        const float dx = sdx[r], dy = sdy[r];
#pragma unroll
        for (int gb = 0; gb < 8; gb++) {
            __nv_bfloat16 h8[8], l8[8];
#pragma unroll
            for (int j = 0; j < 8; j++) {
                const int ch = c0 + gb * 8 + j;
                const float v =
                    fmaxf(fmaf(d0W[2 * ch], dx, fmaf(d0W[2 * ch + 1], dy, d0b[ch])), 0.f);
                bf16_split(v, h8[j], l8[j]);
            }
            const int off = r * RSB + (c0 + gb * 8) * 2;
            *(uint4*)(sAh + off) = *(uint4*)h8;
            *(uint4*)(sAl + off) = *(uint4*)l8;
        }
    }
    CPA_WAIT(1);  // W0 resident (W1 may still be in flight)
    __syncthreads();

    float acc[2][8][4];

    // ---- GEMM1: dist1 (buf0) ----
    ZACC2(acc);
    wgemm2(acc, sb + OFF_AH, sb + OFF_AL, sb + OFF_W0H, sb + OFF_W0L, wm, wn, lane);
    __syncthreads();                       // everyone done reading A & buf0
    copy_w_async(sb + OFF_W0H, sb + OFF_W0L, 2, t);  // prefetch GEMM3 weights into buf0
    CPA_COMMIT();
    gn_mma2<false>(acc, shi, swi, d1g, d1b, sRed, sAh, sAl, wm, wn, lane);
    CPA_WAIT(1);  // W1 resident (W2 may still be in flight)
    __syncthreads();

    // ---- GEMM2: ctx0 d-part (buf1); q+c added from global in GN ----
    ZACC2(acc);
    wgemm2(acc, sb + OFF_AH, sb + OFF_AL, sb + OFF_W1H, sb + OFF_W1L, wm, wn, lane);
    __syncthreads();
    gn_mma2<true>(acc, shi, swi, c0g, c0b, sRed, sAh, sAl, wm, wn, lane);
    CPA_WAIT(0);  // W2 resident
    __syncthreads();

    // ---- GEMM3: ctx1 (buf0) -> scatter ----
    ZACC2(acc);
    wgemm2(acc, sb + OFF_AH, sb + OFF_AL, sb + OFF_W0H, sb + OFF_W0L, wm, wn, lane);
    {
        const int cb = 2 * (lane & 3);
#pragma unroll
        for (int mi = 0; mi < 2; mi++) {
            const int rl = wm * 32 + mi * 16 + (lane >> 2), rh = rl + 8;
            const float* plo = g_a + (size_t)shi[rl] * DD;
            const float* phi = g_a + (size_t)shi[rh] * DD;
#pragma unroll
            for (int ni = 0; ni < 8; ni++) {
                const int col = wn * 64 + ni * 8 + cb;
                redv2(plo + col, acc[mi][ni][0], acc[mi][ni][1]);
                redv2(phi + col, acc[mi][ni][2], acc[mi][ni][3]);
            }
        }
    }
}

#define SMEM_PRE ((2 * TILE * STR + 2 * SWBUF + TILE * 4) * 4)
#define SMEM_POST ((TILE * STR + 2 * SWBUF + TILE * 4) * 4)

extern "C" void kernel_launch(void* const* d_in, const int* in_sizes, int n_in,
                              void* d_out, int out_size) {
    (void)in_sizes; (void)n_in; (void)out_size;
    const float* actors = (const float*)d_in[0];
    const float* nodes = (const float*)d_in[1];
    const float* actor_ctrs = (const float*)d_in[2];
    const float* node_ctrs = (const float*)d_in[3];
    const int* hi = (const int*)d_in[4];
    const int* wi = (const int*)d_in[5];
    const float* d0W = (const float*)d_in[6];
    const float* d0b = (const float*)d_in[7];
    const float* d1W = (const float*)d_in[8];
    const float* d1g = (const float*)d_in[9];
    const float* d1b = (const float*)d_in[10];
    const float* qW = (const float*)d_in[11];
    const float* qg = (const float*)d_in[12];
    const float* qb = (const float*)d_in[13];
    const float* c0W = (const float*)d_in[14];
    const float* c0g = (const float*)d_in[15];
    const float* c0b = (const float*)d_in[16];
    const float* c1W = (const float*)d_in[17];
    const float* aW = (const float*)d_in[18];
    const float* ng = (const float*)d_in[19];
    const float* nb = (const float*)d_in[20];
    const float* lW = (const float*)d_in[21];
    const float* lg = (const float*)d_in[22];
    const float* lb = (const float*)d_in[23];
    float* out = (float*)d_out;

    cudaFuncSetAttribute(pre_kernel, cudaFuncAttributeMaxDynamicSharedMemorySize, SMEM_PRE);
    cudaFuncSetAttribute(node_kernel, cudaFuncAttributeMaxDynamicSharedMemorySize, SMEM_NODE);
    cudaFuncSetAttribute(edge_kernel, cudaFuncAttributeMaxDynamicSharedMemorySize, SMEM_EDGE);
    cudaFuncSetAttribute(post_kernel, cudaFuncAttributeMaxDynamicSharedMemorySize, SMEM_POST);

    for (int blk = 0; blk < 2; blk++) {
        const int off = blk * DD;
        const float* c0Wb = c0W + (size_t)blk * DD * 3 * DD;
        wprep_kernel<<<256, 256>>>(d1W + (size_t)blk * DD * DD, c0Wb,
                                   c1W + (size_t)blk * DD * DD);
        node_kernel<<<NN / TILE, NTH, SMEM_NODE>>>(nodes);
        pre_kernel<<<NA / TILE, NTH, SMEM_PRE>>>(actors, qW + (size_t)blk * DD * DD, qg + off,
                                                 qb + off, c0Wb + DD, aW + (size_t)blk * DD * DD,
                                                 blk);
        edge_kernel<<<NE / TILE, NTH, SMEM_EDGE>>>(actor_ctrs, node_ctrs, hi, wi,
                                                   d0W + (size_t)blk * DD * 2, d0b + off,
                                                   d1g + off, d1b + off, c0g + off, c0b + off);
        post_kernel<<<NA / TILE, NTH, SMEM_POST>>>(actors, ng + off, nb + off,
                                                   lW + (size_t)blk * DD * DD, lg + off, lb + off,
                                                   out, blk);
    }
}